// round 3
// baseline (speedup 1.0000x reference)
#include <cuda_runtime.h>
#include <math.h>

#define HDIM 256
#define MSGD 128
#define OBSD 64
#define ADIM 16
#define G3   768   // 3*HDIM
#define MAXN 20000

// ---------------- scratch (static device globals; no runtime allocation) ----
__device__ __align__(256) float g_x1 [MAXN * HDIM];   // relu(feat@W0+b0)
__device__ __align__(256) float g_x  [MAXN * HDIM];   // relu(x1@W1+b1)
__device__ __align__(256) float g_mx [MAXN * MSGD];   // per-node message precompute
__device__ __align__(256) float g_c  [MAXN * MSGD];   // segment sums -> mean
__device__ __align__(256) float g_cnt[MAXN];          // segment counts
__device__ __align__(256) float g_gi [MAXN * G3];
__device__ __align__(256) float g_gh [MAXN * G3];

// ---------------- generic SGEMM ---------------------------------------------
// C[M x N] = act( A1[M x K1] @ B1[K1 x N] (+ A2[M x K2] @ B2[K2 x N]) + bias )
// A row-major, B row-major (row stride = N). BM=128 BN=64 BK=16, 256 thr, 8x4.
template<bool HAS2, bool RELU>
__global__ void __launch_bounds__(256)
sgemm_kernel(const float* __restrict__ A1, int K1, const float* __restrict__ B1,
             const float* __restrict__ A2, int K2, const float* __restrict__ B2,
             const float* __restrict__ bias, float* __restrict__ C,
             int M, int N)
{
    constexpr int BM = 128, BN = 64, BK = 16, TM = 8, TN = 4;
    __shared__ float As[BK][BM];
    __shared__ float Bs[BK][BN];

    const int tid = threadIdx.x;
    const int tm  = tid >> 4;   // 0..15
    const int tn  = tid & 15;   // 0..15
    const int rowBase = blockIdx.y * BM;
    const int colBase = blockIdx.x * BN;

    float acc[TM][TN];
#pragma unroll
    for (int i = 0; i < TM; i++)
#pragma unroll
        for (int j = 0; j < TN; j++) acc[i][j] = 0.f;

    const float* Ap[2] = {A1, A2};
    const float* Bp[2] = {B1, B2};
    const int    Kp[2] = {K1, K2};
    const int npass = HAS2 ? 2 : 1;

    for (int p = 0; p < npass; p++) {
        const float* __restrict__ A = Ap[p];
        const float* __restrict__ B = Bp[p];
        const int K = Kp[p];

        for (int k0 = 0; k0 < K; k0 += BK) {
            // A tile 128x16 = 512 float4, 2 per thread; store transposed
#pragma unroll
            for (int i = 0; i < 2; i++) {
                int t  = tid * 2 + i;
                int r  = t >> 2;
                int kc = (t & 3) << 2;
                float4 v = make_float4(0.f, 0.f, 0.f, 0.f);
                int grow = rowBase + r;
                if (grow < M)
                    v = *(const float4*)(A + (size_t)grow * K + k0 + kc);
                As[kc + 0][r] = v.x; As[kc + 1][r] = v.y;
                As[kc + 2][r] = v.z; As[kc + 3][r] = v.w;
            }
            // B tile 16x64 = 256 float4, 1 per thread
            {
                int r = tid >> 4;
                int c = (tid & 15) << 2;
                *(float4*)&Bs[r][c] =
                    *(const float4*)(B + (size_t)(k0 + r) * N + colBase + c);
            }
            __syncthreads();

#pragma unroll
            for (int kk = 0; kk < BK; kk++) {
                float a[TM], b[TN];
                *(float4*)&a[0] = *(const float4*)&As[kk][tm * TM];
                *(float4*)&a[4] = *(const float4*)&As[kk][tm * TM + 4];
                *(float4*)&b[0] = *(const float4*)&Bs[kk][tn * TN];
#pragma unroll
                for (int i = 0; i < TM; i++)
#pragma unroll
                    for (int j = 0; j < TN; j++)
                        acc[i][j] = fmaf(a[i], b[j], acc[i][j]);
            }
            __syncthreads();
        }
    }

    float4 bv = *(const float4*)(bias + colBase + tn * TN);
#pragma unroll
    for (int i = 0; i < TM; i++) {
        int r = rowBase + tm * TM + i;
        if (r < M) {
            float4 o;
            o.x = acc[i][0] + bv.x; o.y = acc[i][1] + bv.y;
            o.z = acc[i][2] + bv.z; o.w = acc[i][3] + bv.w;
            if (RELU) {
                o.x = fmaxf(o.x, 0.f); o.y = fmaxf(o.y, 0.f);
                o.z = fmaxf(o.z, 0.f); o.w = fmaxf(o.w, 0.f);
            }
            *(float4*)(C + (size_t)r * N + colBase + tn * TN) = o;
        }
    }
}

// ---------------- edge scatter ----------------------------------------------
// one warp per edge: sums[dst] += mx[src] (128 floats), cnt[dst] += 1
__global__ void scatter_kernel(const float4* __restrict__ mx,
                               const int* __restrict__ src,
                               const int* __restrict__ dst,
                               float* __restrict__ sums,
                               float* __restrict__ cnt, int E)
{
    int w    = (blockIdx.x * blockDim.x + threadIdx.x) >> 5;
    int lane = threadIdx.x & 31;
    if (w >= E) return;
    int s = src[w];
    int d = dst[w];
    float4 v = mx[(size_t)s * 32 + lane];
    float* base = sums + (size_t)d * MSGD + lane * 4;
    atomicAdd(base + 0, v.x);
    atomicAdd(base + 1, v.y);
    atomicAdd(base + 2, v.z);
    atomicAdd(base + 3, v.w);
    if (lane == 0) atomicAdd(cnt + d, 1.0f);
}

__global__ void zero_kernel(float* __restrict__ c, float* __restrict__ cnt, int Nn)
{
    int i = blockIdx.x * blockDim.x + threadIdx.x;
    if (i < Nn * MSGD) c[i] = 0.f;
    if (i < Nn)        cnt[i] = 0.f;
}

__global__ void div_kernel(float* __restrict__ c, const float* __restrict__ cnt, int Nn)
{
    int i = blockIdx.x * blockDim.x + threadIdx.x;
    if (i >= Nn * MSGD) return;
    float d = cnt[i >> 7];            // MSGD = 128
    c[i] = c[i] / fmaxf(d, 1.0f);
}

// ---------------- GRU gates --------------------------------------------------
__global__ void gates_kernel(const float* __restrict__ gi,
                             const float* __restrict__ gh,
                             const float* __restrict__ h,
                             float* __restrict__ hout, int M)
{
    int idx = blockIdx.x * blockDim.x + threadIdx.x;
    if (idx >= M * HDIM) return;
    int n = idx >> 8;                 // HDIM = 256
    int j = idx & 255;
    const float* gin = gi + (size_t)n * G3;
    const float* ghn = gh + (size_t)n * G3;
    float ir = gin[j], iz = gin[HDIM + j], in_ = gin[2 * HDIM + j];
    float hr = ghn[j], hz = ghn[HDIM + j], hn_ = ghn[2 * HDIM + j];
    float r  = 1.f / (1.f + expf(-(ir + hr)));
    float z  = 1.f / (1.f + expf(-(iz + hz)));
    float nn = tanhf(in_ + r * hn_);
    float hp = h[idx];
    hout[idx] = (1.f - z) * nn + z * hp;
}

// ---------------- q = h_new @ out_W + out_b (N=16, K=256) --------------------
__global__ void __launch_bounds__(256)
qout_kernel(const float* __restrict__ hn, const float* __restrict__ W,
            const float* __restrict__ b, float* __restrict__ q, int M)
{
    __shared__ float Ws[HDIM * ADIM];
    int tid = threadIdx.x;
    for (int i = tid; i < HDIM * ADIM; i += 256) Ws[i] = W[i];
    __syncthreads();

    int n = blockIdx.x * 256 + tid;
    if (n >= M) return;
    float acc[ADIM];
#pragma unroll
    for (int c = 0; c < ADIM; c++) acc[c] = b[c];
    const float* hr = hn + (size_t)n * HDIM;
    for (int k = 0; k < HDIM; k++) {
        float hv = hr[k];
#pragma unroll
        for (int c = 0; c < ADIM; c++) acc[c] = fmaf(hv, Ws[k * ADIM + c], acc[c]);
    }
    float* qr = q + (size_t)n * ADIM;
#pragma unroll
    for (int c = 0; c < ADIM; c++) qr[c] = acc[c];
}

// ---------------- launch ------------------------------------------------------
extern "C" void kernel_launch(void* const* d_in, const int* in_sizes, int n_in,
                              void* d_out, int out_size)
{
    const float* feat = (const float*)d_in[0];
    const float* h    = (const float*)d_in[1];
    const int*   src  = (const int*)d_in[2];
    const int*   dst  = (const int*)d_in[3];
    const float* eW0  = (const float*)d_in[4];
    const float* eb0  = (const float*)d_in[5];
    const float* eW1  = (const float*)d_in[6];
    const float* eb1  = (const float*)d_in[7];
    const float* mW   = (const float*)d_in[8];
    const float* mb   = (const float*)d_in[9];
    const float* Wih  = (const float*)d_in[10];
    const float* Whh  = (const float*)d_in[11];
    const float* bih  = (const float*)d_in[12];
    const float* bhh  = (const float*)d_in[13];
    const float* oW   = (const float*)d_in[14];
    const float* ob   = (const float*)d_in[15];

    const int Nn = in_sizes[1] / HDIM;   // 20000
    const int E  = in_sizes[2];          // 640000

    float *x1, *x, *mx, *c, *cnt, *gi, *gh;
    cudaGetSymbolAddress((void**)&x1,  g_x1);
    cudaGetSymbolAddress((void**)&x,   g_x);
    cudaGetSymbolAddress((void**)&mx,  g_mx);
    cudaGetSymbolAddress((void**)&c,   g_c);
    cudaGetSymbolAddress((void**)&cnt, g_cnt);
    cudaGetSymbolAddress((void**)&gi,  g_gi);
    cudaGetSymbolAddress((void**)&gh,  g_gh);

    float* out = (float*)d_out;
    float* q_out;
    float* h_out;
    if (out_size >= Nn * (ADIM + HDIM)) {        // (q, h_new) concatenated
        q_out = out;
        h_out = out + (size_t)Nn * ADIM;
    } else if (out_size == Nn * HDIM) {          // only h_new requested
        h_out = out;
        q_out = x1;                              // x1 is free by then
    } else {                                     // only q requested
        q_out = out;
        h_out = x1;
    }

    const int gy = (Nn + 127) / 128;
    dim3 blk(256);

    // x1 = relu(feat @ enc_W0 + enc_b0)     [N,64]@[64,256]
    sgemm_kernel<false, true><<<dim3(HDIM / 64, gy), blk>>>(
        feat, OBSD, eW0, nullptr, 0, nullptr, eb0, x1, Nn, HDIM);

    // x = relu(x1 @ enc_W1 + enc_b1)        [N,256]@[256,256]
    sgemm_kernel<false, true><<<dim3(HDIM / 64, gy), blk>>>(
        x1, HDIM, eW1, nullptr, 0, nullptr, eb1, x, Nn, HDIM);

    // mx = x @ Wx + h @ Wh + msg_b          (per-node message precompute)
    sgemm_kernel<true, false><<<dim3(MSGD / 64, gy), blk>>>(
        x, HDIM, mW, h, HDIM, mW + (size_t)HDIM * MSGD, mb, mx, Nn, MSGD);

    // segment mean over edges
    zero_kernel<<<(Nn * MSGD + 255) / 256, 256>>>(c, cnt, Nn);
    scatter_kernel<<<(E * 32 + 255) / 256, 256>>>((const float4*)mx, src, dst, c, cnt, E);
    div_kernel<<<(Nn * MSGD + 255) / 256, 256>>>(c, cnt, Nn);

    // gi = [x | c] @ gru_Wih + bih          [N,384]@[384,768]
    sgemm_kernel<true, false><<<dim3(G3 / 64, gy), blk>>>(
        x, HDIM, Wih, c, MSGD, Wih + (size_t)HDIM * G3, bih, gi, Nn, G3);

    // gh = h @ gru_Whh + bhh                [N,256]@[256,768]
    sgemm_kernel<false, false><<<dim3(G3 / 64, gy), blk>>>(
        h, HDIM, Whh, nullptr, 0, nullptr, bhh, gh, Nn, G3);

    // GRU gates -> h_new
    gates_kernel<<<(Nn * HDIM + 255) / 256, 256>>>(gi, gh, h, h_out, Nn);

    // q = h_new @ out_W + out_b
    qout_kernel<<<(Nn + 255) / 256, 256>>>(h_out, oW, ob, q_out, Nn);
}

// round 5
// speedup vs baseline: 1.3990x; 1.3990x over previous
#include <cuda_runtime.h>
#include <mma.h>
#include <math.h>

using namespace nvcuda;

#define HDIM 256
#define MSGD 128
#define OBSD 64
#define ADIM 16
#define G3   768   // 3*HDIM
#define MAXN 20000

// ---------------- scratch (static device globals; no runtime allocation) ----
__device__ __align__(256) float g_x1 [MAXN * HDIM];
__device__ __align__(256) float g_x  [MAXN * HDIM];
__device__ __align__(256) float g_mx [MAXN * MSGD];
__device__ __align__(256) float g_c  [MAXN * MSGD];
__device__ __align__(256) float g_cnt[MAXN];
__device__ __align__(256) float g_gi [MAXN * G3];
__device__ __align__(256) float g_gh [MAXN * G3];

// ---------------- tf32 WMMA GEMM ---------------------------------------------
// C[M x N] = act( A1@B1 (+ A2@B2) + bias ), A,B,C row-major.
// BM=128 BN=64 BK=32, 256 threads = 8 warps, warp tile 32x32 (2x2 wmma 16x16).
#define LDA 40   // 32 + 8 pad
#define LDB 72   // 64 + 8 pad

template<bool HAS2, bool RELU>
__global__ void __launch_bounds__(256)
tgemm_kernel(const float* __restrict__ A1, int K1, const float* __restrict__ B1,
             const float* __restrict__ A2, int K2, const float* __restrict__ B2,
             const float* __restrict__ bias, float* __restrict__ C,
             int M, int N)
{
    constexpr int BM = 128, BN = 64, BK = 32;
    __shared__ float As[BM * LDA];
    __shared__ float Bs[BK * LDB];
    __shared__ float BiasS[16 * LDB];

    const int tid     = threadIdx.x;
    const int warpId  = tid >> 5;
    const int wy      = warpId & 3;        // 0..3 : m offset wy*32
    const int wx      = warpId >> 2;       // 0..1 : n offset wx*32
    const int rowBase = blockIdx.y * BM;
    const int colBase = blockIdx.x * BN;

    // bias tile: 16 identical rows of bias[colBase .. +64)
    for (int i = tid; i < 16 * BN; i += 256) {
        int r = i >> 6, cc = i & 63;
        BiasS[r * LDB + cc] = bias[colBase + cc];
    }
    __syncthreads();

    wmma::fragment<wmma::accumulator, 16, 16, 8, float> acc[2][2];
#pragma unroll
    for (int i = 0; i < 2; i++)
#pragma unroll
        for (int j = 0; j < 2; j++)
            wmma::load_matrix_sync(acc[i][j],
                &BiasS[wx * 32 + j * 16], LDB, wmma::mem_row_major);

    const float* Ap[2] = {A1, A2};
    const float* Bp[2] = {B1, B2};
    const int    Kp[2] = {K1, K2};
    const int npass = HAS2 ? 2 : 1;

    for (int p = 0; p < npass; p++) {
        const float* __restrict__ A = Ap[p];
        const float* __restrict__ B = Bp[p];
        const int K = Kp[p];

        for (int k0 = 0; k0 < K; k0 += BK) {
            __syncthreads();
            // A tile: 128x32 = 1024 float4, 4 per thread
#pragma unroll
            for (int i = 0; i < 4; i++) {
                int idx = tid + i * 256;
                int r   = idx >> 3;          // 0..127
                int c4  = (idx & 7) << 2;    // 0..28
                float4 v = make_float4(0.f, 0.f, 0.f, 0.f);
                int grow = rowBase + r;
                if (grow < M)
                    v = *(const float4*)(A + (size_t)grow * K + k0 + c4);
                *(float4*)&As[r * LDA + c4] = v;
            }
            // B tile: 32x64 = 512 float4, 2 per thread
#pragma unroll
            for (int i = 0; i < 2; i++) {
                int idx = tid + i * 256;
                int r   = idx >> 4;          // 0..31
                int c4  = (idx & 15) << 2;   // 0..60
                *(float4*)&Bs[r * LDB + c4] =
                    *(const float4*)(B + (size_t)(k0 + r) * N + colBase + c4);
            }
            __syncthreads();

#pragma unroll
            for (int kk = 0; kk < BK / 8; kk++) {
                wmma::fragment<wmma::matrix_a, 16, 16, 8,
                               wmma::precision::tf32, wmma::row_major> af[2];
                wmma::fragment<wmma::matrix_b, 16, 16, 8,
                               wmma::precision::tf32, wmma::row_major> bf[2];
#pragma unroll
                for (int i = 0; i < 2; i++) {
                    wmma::load_matrix_sync(af[i],
                        &As[(wy * 32 + i * 16) * LDA + kk * 8], LDA);
#pragma unroll
                    for (int e = 0; e < af[i].num_elements; e++)
                        af[i].x[e] = wmma::__float_to_tf32(af[i].x[e]);
                }
#pragma unroll
                for (int j = 0; j < 2; j++) {
                    wmma::load_matrix_sync(bf[j],
                        &Bs[(kk * 8) * LDB + wx * 32 + j * 16], LDB);
#pragma unroll
                    for (int e = 0; e < bf[j].num_elements; e++)
                        bf[j].x[e] = wmma::__float_to_tf32(bf[j].x[e]);
                }
#pragma unroll
                for (int i = 0; i < 2; i++)
#pragma unroll
                    for (int j = 0; j < 2; j++)
                        wmma::mma_sync(acc[i][j], af[i], bf[j], acc[i][j]);
            }
        }
    }

#pragma unroll
    for (int i = 0; i < 2; i++) {
        int gm = rowBase + wy * 32 + i * 16;
        if (gm < M) {    // M is a multiple of 16: tile fully valid or fully out
#pragma unroll
            for (int j = 0; j < 2; j++) {
                if (RELU) {
#pragma unroll
                    for (int e = 0; e < acc[i][j].num_elements; e++)
                        acc[i][j].x[e] = fmaxf(acc[i][j].x[e], 0.f);
                }
                wmma::store_matrix_sync(
                    C + (size_t)gm * N + colBase + wx * 32 + j * 16,
                    acc[i][j], N, wmma::mem_row_major);
            }
        }
    }
}

// ---------------- edge scatter (vector red) ----------------------------------
// one warp per edge: sums[dst] += mx[src] (128 floats via v4 red), cnt[dst]+=1
__global__ void scatter_kernel(const float4* __restrict__ mx,
                               const int* __restrict__ src,
                               const int* __restrict__ dst,
                               float* __restrict__ sums,
                               float* __restrict__ cnt, int E)
{
    int w    = (blockIdx.x * blockDim.x + threadIdx.x) >> 5;
    int lane = threadIdx.x & 31;
    if (w >= E) return;
    int s = src[w];
    int d = dst[w];
    float4 v = mx[(size_t)s * 32 + lane];
    float* base = sums + (size_t)d * MSGD + lane * 4;
    asm volatile("red.global.add.v4.f32 [%0], {%1, %2, %3, %4};"
                 :: "l"(base), "f"(v.x), "f"(v.y), "f"(v.z), "f"(v.w)
                 : "memory");
    if (lane == 0) atomicAdd(cnt + d, 1.0f);
}

__global__ void div_kernel(float* __restrict__ c, const float* __restrict__ cnt, int Nn)
{
    int i = blockIdx.x * blockDim.x + threadIdx.x;
    if (i >= Nn * MSGD) return;
    float d = cnt[i >> 7];            // MSGD = 128
    c[i] = c[i] / fmaxf(d, 1.0f);
}

// ---------------- GRU gates --------------------------------------------------
__global__ void gates_kernel(const float* __restrict__ gi,
                             const float* __restrict__ gh,
                             const float* __restrict__ h,
                             float* __restrict__ hout, int M)
{
    int idx = blockIdx.x * blockDim.x + threadIdx.x;
    if (idx >= M * HDIM) return;
    int n = idx >> 8;                 // HDIM = 256
    int j = idx & 255;
    const float* gin = gi + (size_t)n * G3;
    const float* ghn = gh + (size_t)n * G3;
    float ir = gin[j], iz = gin[HDIM + j], in_ = gin[2 * HDIM + j];
    float hr = ghn[j], hz = ghn[HDIM + j], hn_ = ghn[2 * HDIM + j];
    float r  = 1.f / (1.f + expf(-(ir + hr)));
    float z  = 1.f / (1.f + expf(-(iz + hz)));
    float nn = tanhf(in_ + r * hn_);
    float hp = h[idx];
    hout[idx] = (1.f - z) * nn + z * hp;
}

// ---------------- q = h_new @ out_W + out_b (N=16, K=256) --------------------
__global__ void __launch_bounds__(256)
qout_kernel(const float* __restrict__ hn, const float* __restrict__ W,
            const float* __restrict__ b, float* __restrict__ q, int M)
{
    __shared__ float Ws[HDIM * ADIM];
    int tid = threadIdx.x;
    for (int i = tid; i < HDIM * ADIM; i += 256) Ws[i] = W[i];
    __syncthreads();

    int n = blockIdx.x * 256 + tid;
    if (n >= M) return;
    float acc[ADIM];
#pragma unroll
    for (int c = 0; c < ADIM; c++) acc[c] = b[c];
    const float* hr = hn + (size_t)n * HDIM;
    for (int k = 0; k < HDIM; k++) {
        float hv = hr[k];
#pragma unroll
        for (int c = 0; c < ADIM; c++) acc[c] = fmaf(hv, Ws[k * ADIM + c], acc[c]);
    }
    float* qr = q + (size_t)n * ADIM;
#pragma unroll
    for (int c = 0; c < ADIM; c++) qr[c] = acc[c];
}

// ---------------- launch ------------------------------------------------------
extern "C" void kernel_launch(void* const* d_in, const int* in_sizes, int n_in,
                              void* d_out, int out_size)
{
    const float* feat = (const float*)d_in[0];
    const float* h    = (const float*)d_in[1];
    const int*   src  = (const int*)d_in[2];
    const int*   dst  = (const int*)d_in[3];
    const float* eW0  = (const float*)d_in[4];
    const float* eb0  = (const float*)d_in[5];
    const float* eW1  = (const float*)d_in[6];
    const float* eb1  = (const float*)d_in[7];
    const float* mW   = (const float*)d_in[8];
    const float* mb   = (const float*)d_in[9];
    const float* Wih  = (const float*)d_in[10];
    const float* Whh  = (const float*)d_in[11];
    const float* bih  = (const float*)d_in[12];
    const float* bhh  = (const float*)d_in[13];
    const float* oW   = (const float*)d_in[14];
    const float* ob   = (const float*)d_in[15];

    const int Nn = in_sizes[1] / HDIM;   // 20000
    const int E  = in_sizes[2];          // 640000

    float *x1, *x, *mx, *c, *cnt, *gi, *gh;
    cudaGetSymbolAddress((void**)&x1,  g_x1);
    cudaGetSymbolAddress((void**)&x,   g_x);
    cudaGetSymbolAddress((void**)&mx,  g_mx);
    cudaGetSymbolAddress((void**)&c,   g_c);
    cudaGetSymbolAddress((void**)&cnt, g_cnt);
    cudaGetSymbolAddress((void**)&gi,  g_gi);
    cudaGetSymbolAddress((void**)&gh,  g_gh);

    float* out = (float*)d_out;
    float* q_out;
    float* h_out;
    if (out_size >= Nn * (ADIM + HDIM)) {        // (q, h_new) concatenated
        q_out = out;
        h_out = out + (size_t)Nn * ADIM;
    } else if (out_size == Nn * HDIM) {
        h_out = out;
        q_out = x1;
    } else {
        q_out = out;
        h_out = x1;
    }

    const int gy = (Nn + 127) / 128;
    dim3 blk(256);

    // x1 = relu(feat @ enc_W0 + enc_b0)     [N,64]@[64,256]
    tgemm_kernel<false, true><<<dim3(HDIM / 64, gy), blk>>>(
        feat, OBSD, eW0, nullptr, 0, nullptr, eb0, x1, Nn, HDIM);

    // x = relu(x1 @ enc_W1 + enc_b1)        [N,256]@[256,256]
    tgemm_kernel<false, true><<<dim3(HDIM / 64, gy), blk>>>(
        x1, HDIM, eW1, nullptr, 0, nullptr, eb1, x, Nn, HDIM);

    // mx = x @ Wx + h @ Wh + msg_b          (per-node message precompute)
    tgemm_kernel<true, false><<<dim3(MSGD / 64, gy), blk>>>(
        x, HDIM, mW, h, HDIM, mW + (size_t)HDIM * MSGD, mb, mx, Nn, MSGD);

    // segment mean over edges
    cudaMemsetAsync(c, 0, (size_t)Nn * MSGD * sizeof(float));
    cudaMemsetAsync(cnt, 0, (size_t)Nn * sizeof(float));
    scatter_kernel<<<(E * 32 + 255) / 256, 256>>>((const float4*)mx, src, dst, c, cnt, E);
    div_kernel<<<(Nn * MSGD + 255) / 256, 256>>>(c, cnt, Nn);

    // gi = [x | c] @ gru_Wih + bih          [N,384]@[384,768]
    tgemm_kernel<true, false><<<dim3(G3 / 64, gy), blk>>>(
        x, HDIM, Wih, c, MSGD, Wih + (size_t)HDIM * G3, bih, gi, Nn, G3);

    // gh = h @ gru_Whh + bhh                [N,256]@[256,768]
    tgemm_kernel<false, false><<<dim3(G3 / 64, gy), blk>>>(
        h, HDIM, Whh, nullptr, 0, nullptr, bhh, gh, Nn, G3);

    // GRU gates -> h_new
    gates_kernel<<<(Nn * HDIM + 255) / 256, 256>>>(gi, gh, h, h_out, Nn);

    // q = h_new @ out_W + out_b
    qout_kernel<<<(Nn + 255) / 256, 256>>>(h_out, oW, ob, q_out, Nn);
}